// round 1
// baseline (speedup 1.0000x reference)
#include <cuda_runtime.h>
#include <cuda_bf16.h>
#include <math.h>
#include <stdint.h>

// Problem constants (hardcoded — all dims divide the tile sizes evenly).
constexpr int Bsz = 8, Ssz = 1024, Dsz = 1024, Hsz = 16, DKsz = 64, FFsz = 4096;
constexpr int MROWS = Bsz * Ssz;           // 8192
constexpr int NQKV  = 3 * Hsz * DKsz;      // 3072

// ---------------------------------------------------------------------------
// Static device scratch (allocation-free per harness rules)
// ---------------------------------------------------------------------------
__device__ int   g_mask_mode;                                  // 0=f32,1=i32,2=u8,3=bf16
__device__ float g_Wpack[(size_t)Dsz * NQKV];                  // packed [D, 3*H*DK]
__device__ float g_QKV[(size_t)MROWS * NQKV];                  // [B*S, 3072]
__device__ float g_S[(size_t)Bsz * Hsz * Ssz * Ssz];           // scores / probs (537MB)
__device__ float g_O[(size_t)MROWS * Dsz];                     // attn out (heads concat)
__device__ float g_ATT[(size_t)MROWS * Dsz];                   // after fc proj
__device__ float g_X1[(size_t)MROWS * Dsz];                    // after LN1
__device__ float g_H1[(size_t)MROWS * FFsz];                   // FFN hidden
__device__ float g_H2[(size_t)MROWS * Dsz];                    // FFN out

// ---------------------------------------------------------------------------
// Fast exp on the FMA pipe (avoids MUFU throughput wall). x <= ~3 here.
// exp(x) = 2^(x*log2e); degree-7 Taylor of 2^f on [0,1), |rel err| ~1e-6.
// ---------------------------------------------------------------------------
__device__ __forceinline__ float fast_exp(float x) {
    x = fmaxf(x, -87.0f);
    float t  = x * 1.4426950408889634f;
    float fi = floorf(t);
    float f  = t - fi;
    float p = 1.5252733e-5f;
    p = fmaf(p, f, 1.5403530e-4f);
    p = fmaf(p, f, 1.3333558e-3f);
    p = fmaf(p, f, 9.6181291e-3f);
    p = fmaf(p, f, 5.5504109e-2f);
    p = fmaf(p, f, 2.4022651e-1f);
    p = fmaf(p, f, 6.9314718e-1f);
    p = fmaf(p, f, 1.0f);
    return __int_as_float(__float_as_int(p) + ((int)fi << 23));
}

// ---------------------------------------------------------------------------
// Mask dtype detector: classify the first 1024 words deterministically.
// f32 pattern {0,0x3F800000}; bf16 pattern adds {0x3F803F80,0x00003F80};
// i32 pattern {0,1}; otherwise u8. (f32 checked first; misclass prob ~2^-1000.)
// ---------------------------------------------------------------------------
__global__ void detect_mask_kernel(const unsigned int* __restrict__ w) {
    __shared__ int flags[3];
    if (threadIdx.x < 3) flags[threadIdx.x] = 1;
    __syncthreads();
    int f32ok = 1, bf16ok = 1, i32ok = 1;
    for (int i = threadIdx.x; i < 1024; i += blockDim.x) {
        unsigned u = w[i];
        if (!(u == 0u || u == 0x3F800000u)) f32ok = 0;
        if (!(u == 0u || u == 0x3F800000u || u == 0x3F803F80u || u == 0x00003F80u)) bf16ok = 0;
        if (u > 1u) i32ok = 0;
    }
    if (!f32ok)  atomicAnd(&flags[0], 0);
    if (!bf16ok) atomicAnd(&flags[1], 0);
    if (!i32ok)  atomicAnd(&flags[2], 0);
    __syncthreads();
    if (threadIdx.x == 0)
        g_mask_mode = flags[0] ? 0 : (flags[1] ? 3 : (flags[2] ? 1 : 2));
}

__device__ __forceinline__ bool mask_true(const void* mask, long long off, int mode) {
    if (mode == 2) return ((const unsigned char*)mask)[off] != 0;
    if (mode == 1) return ((const int*)mask)[off] != 0;
    if (mode == 3) return ((const unsigned short*)mask)[off] != 0;
    return ((const float*)mask)[off] != 0.0f;
}

// ---------------------------------------------------------------------------
// Pack wq|wk|wv ([H,D,64] each) into [D, 3072] (n-contiguous) for one big GEMM
// ---------------------------------------------------------------------------
__global__ void pack_w_kernel(const float* __restrict__ wq,
                              const float* __restrict__ wk,
                              const float* __restrict__ wv) {
    long long i = (long long)blockIdx.x * blockDim.x + threadIdx.x;
    if (i >= (long long)Dsz * NQKV) return;
    int col = (int)(i % NQKV);
    int d   = (int)(i / NQKV);
    int sel = col / 1024;
    int hr  = col % 1024;
    int h   = hr / 64, e = hr % 64;
    const float* w = (sel == 0) ? wq : (sel == 1) ? wk : wv;
    g_Wpack[i] = w[((long long)h * Dsz + d) * 64 + e];
}

// ---------------------------------------------------------------------------
// Generic tiled SGEMM. A: row-major [M,K] (lda). B: if BT, [N,K] k-contig (NT);
// else [K,N] n-contig (NN). C row-major (ldc). Batched over z: b=z>>4, h=z&15.
// EPI: 0 none, 1 +bias, 2 +bias+relu, 3 mask-fill(-125)/scale(0.125) for scores.
// All dims are exact multiples of the tiles — no bounds checks.
// ---------------------------------------------------------------------------
template<int BM, int BN, int BK, bool BT, int EPI>
__global__ __launch_bounds__(256)
void gemm_k(const float* __restrict__ A, int lda, long long sAb, long long sAh,
            const float* __restrict__ B, int ldb, long long sBb, long long sBh,
            float* __restrict__ C, int ldc, long long sCb, long long sCh,
            int K, const float* __restrict__ bias, const void* __restrict__ mask) {
    static_assert(BM == 128 && BK == 8, "loader assumes BM=128, BK=8");
    constexpr int TM = 8;
    constexpr int TN = (BM * BN) / (256 * TM);

    __shared__ float As[BK][BM];
    __shared__ float Bs[BK][BN];

    const int tid = threadIdx.x;
    const int bz = blockIdx.z;
    const int bb = bz >> 4, hh = bz & 15;

    const float* Ab = A + bb * sAb + hh * sAh + (long long)blockIdx.y * BM * lda;
    const float* Bb = B + bb * sBb + hh * sBh;
    float*       Cb = C + bb * sCb + hh * sCh;
    const int n0 = blockIdx.x * BN;

    float acc[TM][TN];
#pragma unroll
    for (int i = 0; i < TM; i++)
#pragma unroll
        for (int j = 0; j < TN; j++) acc[i][j] = 0.0f;

    const int tx = tid % (BN / TN);
    const int ty = tid / (BN / TN);
    const int row = ty * TM;
    const int col = tx * TN;

    // A loader: one float4 along K per thread (BM*BK/4 == 256)
    const int a_m = tid >> 1;
    const int a_k = (tid & 1) * 4;

    for (int k0 = 0; k0 < K; k0 += BK) {
        float4 av = *(const float4*)(Ab + (long long)a_m * lda + k0 + a_k);
        As[a_k + 0][a_m] = av.x;
        As[a_k + 1][a_m] = av.y;
        As[a_k + 2][a_m] = av.z;
        As[a_k + 3][a_m] = av.w;

        if (!BT) {
            constexpr int BV = BK * BN / 4;
            if (BV == 256 || tid < BV) {
                int b_k = tid / (BN / 4);
                int b_n = (tid % (BN / 4)) * 4;
                float4 bv = *(const float4*)(Bb + (long long)(k0 + b_k) * ldb + n0 + b_n);
                *(float4*)&Bs[b_k][b_n] = bv;
            }
        } else {
            constexpr int BV = BN * BK / 4;
            if (BV == 256 || tid < BV) {
                int b_n = tid >> 1;
                int b_k = (tid & 1) * 4;
                float4 bv = *(const float4*)(Bb + (long long)(n0 + b_n) * ldb + k0 + b_k);
                Bs[b_k + 0][b_n] = bv.x;
                Bs[b_k + 1][b_n] = bv.y;
                Bs[b_k + 2][b_n] = bv.z;
                Bs[b_k + 3][b_n] = bv.w;
            }
        }
        __syncthreads();

#pragma unroll
        for (int kk = 0; kk < BK; kk++) {
            float ar[TM], br[TN];
#pragma unroll
            for (int i = 0; i < TM; i += 4)
                *(float4*)&ar[i] = *(const float4*)&As[kk][row + i];
#pragma unroll
            for (int j = 0; j < TN; j += 4)
                *(float4*)&br[j] = *(const float4*)&Bs[kk][col + j];
#pragma unroll
            for (int i = 0; i < TM; i++)
#pragma unroll
                for (int j = 0; j < TN; j++)
                    acc[i][j] = fmaf(ar[i], br[j], acc[i][j]);
        }
        __syncthreads();
    }

    // Epilogue
    const long long mrow0 = (long long)blockIdx.y * BM + row;
    int mode = 0;
    long long mbase = 0;
    if (EPI == 3) {
        mode = g_mask_mode;
        mbase = (long long)bb * Ssz * Ssz;
    }
#pragma unroll
    for (int i = 0; i < TM; i++) {
        long long gm = mrow0 + i;
        float* crow = Cb + gm * ldc + n0 + col;
#pragma unroll
        for (int j = 0; j < TN; j += 4) {
            float4 v;
            float vv[4];
#pragma unroll
            for (int u = 0; u < 4; u++) {
                float a = acc[i][j + u];
                int gn = n0 + col + j + u;
                if (EPI == 1) a += bias[gn];
                else if (EPI == 2) { a += bias[gn]; a = fmaxf(a, 0.0f); }
                else if (EPI == 3) {
                    bool mv = mask_true(mask, mbase + gm * Ssz + gn, mode);
                    a = mv ? a * 0.125f : -125.0f;
                }
                vv[u] = a;
            }
            v.x = vv[0]; v.y = vv[1]; v.z = vv[2]; v.w = vv[3];
            *(float4*)&crow[j] = v;
        }
    }
}

// ---------------------------------------------------------------------------
// Column softmax over the QUERY axis: for each (b,h,k), softmax over q (1024).
// Block: 64 columns x (b,h); 256 threads = 64 cols * 4 row-groups. In-place.
// ---------------------------------------------------------------------------
__global__ __launch_bounds__(256)
void col_softmax_kernel(float* __restrict__ S) {
    const int c = threadIdx.x & 63;
    const int r = threadIdx.x >> 6;   // 0..3
    float* base = S + (long long)blockIdx.y * ((long long)Ssz * Ssz)
                    + blockIdx.x * 64 + c;

    float m = -3.0e38f, l = 0.0f;
    for (int q = r; q < Ssz; q += 4) {
        float v = base[(long long)q * Ssz];
        float mn = fmaxf(m, v);
        l = l * fast_exp(m - mn) + fast_exp(v - mn);
        m = mn;
    }

    __shared__ float sm[4][64], sl[4][64];
    sm[r][c] = m; sl[r][c] = l;
    __syncthreads();
    if (r == 0) {
        float M = m, L = l;
#pragma unroll
        for (int i = 1; i < 4; i++) {
            float m2 = sm[i][c], l2 = sl[i][c];
            float mn = fmaxf(M, m2);
            L = L * fast_exp(M - mn) + l2 * fast_exp(m2 - mn);
            M = mn;
        }
        sm[0][c] = M;
        sl[0][c] = 1.0f / L;
    }
    __syncthreads();
    const float M = sm[0][c];
    const float inv = sl[0][c];
    for (int q = r; q < Ssz; q += 4) {
        long long off = (long long)q * Ssz;
        base[off] = fast_exp(base[off] - M) * inv;
    }
}

// ---------------------------------------------------------------------------
// Fused residual-add + LayerNorm. out = LN(a + b) * g + beta. Row = 1024.
// ---------------------------------------------------------------------------
__global__ __launch_bounds__(256)
void ln_kernel(const float* __restrict__ a, const float* __restrict__ b,
               const float* __restrict__ g, const float* __restrict__ beta,
               float* __restrict__ out) {
    const int t = threadIdx.x;
    const long long base = (long long)blockIdx.x * Dsz;
    float v[4];
    float s = 0.0f;
#pragma unroll
    for (int j = 0; j < 4; j++) {
        int idx = t + j * 256;
        v[j] = a[base + idx] + b[base + idx];
        s += v[j];
    }
    __shared__ float red[8];
    __shared__ float bc;
    // reduce sum
#pragma unroll
    for (int o = 16; o; o >>= 1) s += __shfl_xor_sync(0xffffffffu, s, o);
    if ((t & 31) == 0) red[t >> 5] = s;
    __syncthreads();
    if (t == 0) {
        float tt = 0;
#pragma unroll
        for (int i = 0; i < 8; i++) tt += red[i];
        bc = tt * (1.0f / 1024.0f);
    }
    __syncthreads();
    const float mu = bc;
    float q = 0.0f;
#pragma unroll
    for (int j = 0; j < 4; j++) {
        float d = v[j] - mu;
        q += d * d;
    }
    __syncthreads();  // red reuse hazard
#pragma unroll
    for (int o = 16; o; o >>= 1) q += __shfl_xor_sync(0xffffffffu, q, o);
    if ((t & 31) == 0) red[t >> 5] = q;
    __syncthreads();
    __shared__ float bc2;
    if (t == 0) {
        float tt = 0;
#pragma unroll
        for (int i = 0; i < 8; i++) tt += red[i];
        bc2 = rsqrtf(tt * (1.0f / 1024.0f) + 1e-5f);
    }
    __syncthreads();
    const float rs = bc2;
#pragma unroll
    for (int j = 0; j < 4; j++) {
        int idx = t + j * 256;
        out[base + idx] = (v[j] - mu) * rs * g[idx] + beta[idx];
    }
}

// ---------------------------------------------------------------------------
// Launch
// ---------------------------------------------------------------------------
extern "C" void kernel_launch(void* const* d_in, const int* in_sizes, int n_in,
                              void* d_out, int out_size) {
    const float* x     = (const float*)d_in[0];
    const void*  mask  = d_in[1];
    const float* wq    = (const float*)d_in[2];
    const float* wk    = (const float*)d_in[3];
    const float* wv    = (const float*)d_in[4];
    const float* fc_w  = (const float*)d_in[5];
    const float* fc_b  = (const float*)d_in[6];
    const float* w1    = (const float*)d_in[7];
    const float* b1    = (const float*)d_in[8];
    const float* w2    = (const float*)d_in[9];
    const float* b2    = (const float*)d_in[10];
    const float* ln1_g = (const float*)d_in[11];
    const float* ln1_b = (const float*)d_in[12];
    const float* ln2_g = (const float*)d_in[13];
    const float* ln2_b = (const float*)d_in[14];
    float* out = (float*)d_out;

    float *Wpack, *QKV, *S, *O, *ATT, *X1, *H1, *H2;
    cudaGetSymbolAddress((void**)&Wpack, g_Wpack);
    cudaGetSymbolAddress((void**)&QKV,   g_QKV);
    cudaGetSymbolAddress((void**)&S,     g_S);
    cudaGetSymbolAddress((void**)&O,     g_O);
    cudaGetSymbolAddress((void**)&ATT,   g_ATT);
    cudaGetSymbolAddress((void**)&X1,    g_X1);
    cudaGetSymbolAddress((void**)&H1,    g_H1);
    cudaGetSymbolAddress((void**)&H2,    g_H2);

    detect_mask_kernel<<<1, 256>>>((const unsigned int*)mask);
    pack_w_kernel<<<(Dsz * NQKV + 255) / 256, 256>>>(wq, wk, wv);

    // G1: QKV = x @ Wpack   [8192,1024]x[1024,3072]
    gemm_k<128, 128, 8, false, 0><<<dim3(NQKV / 128, MROWS / 128, 1), 256>>>(
        x, Dsz, 0, 0, Wpack, NQKV, 0, 0, QKV, NQKV, 0, 0, Dsz, nullptr, nullptr);

    // G2: scores per (b,h): S = Q @ K^T, epilogue: mask-fill(-125) + *0.125
    gemm_k<128, 128, 8, true, 3><<<dim3(Ssz / 128, Ssz / 128, Bsz * Hsz), 256>>>(
        QKV, NQKV, (long long)Ssz * NQKV, 64,
        QKV + 1024, NQKV, (long long)Ssz * NQKV, 64,
        S, Ssz, (long long)Hsz * Ssz * Ssz, (long long)Ssz * Ssz,
        DKsz, nullptr, mask);

    // softmax over query axis (columns of each [Sq,Sk] matrix), in place
    col_softmax_kernel<<<dim3(Ssz / 64, Bsz * Hsz), 256>>>(S);

    // G3: O = P @ V per (b,h): [1024,1024]x[1024,64] -> heads-concat layout
    gemm_k<128, 64, 8, false, 0><<<dim3(1, Ssz / 128, Bsz * Hsz), 256>>>(
        S, Ssz, (long long)Hsz * Ssz * Ssz, (long long)Ssz * Ssz,
        QKV + 2048, NQKV, (long long)Ssz * NQKV, 64,
        O, Dsz, (long long)Ssz * Dsz, 64,
        Ssz, nullptr, nullptr);

    // G4: ATT = O @ fc_w^T + fc_b
    gemm_k<128, 128, 8, true, 1><<<dim3(Dsz / 128, MROWS / 128, 1), 256>>>(
        O, Dsz, 0, 0, fc_w, Dsz, 0, 0, ATT, Dsz, 0, 0, Dsz, fc_b, nullptr);

    // LN1: X1 = LN(ATT + x)
    ln_kernel<<<MROWS, 256>>>(ATT, x, ln1_g, ln1_b, X1);

    // G5: H1 = relu(X1 @ w1^T + b1)
    gemm_k<128, 128, 8, true, 2><<<dim3(FFsz / 128, MROWS / 128, 1), 256>>>(
        X1, Dsz, 0, 0, w1, Dsz, 0, 0, H1, FFsz, 0, 0, Dsz, b1, nullptr);

    // G6: H2 = H1 @ w2^T + b2
    gemm_k<128, 128, 8, true, 1><<<dim3(Dsz / 128, MROWS / 128, 1), 256>>>(
        H1, FFsz, 0, 0, w2, FFsz, 0, 0, H2, Dsz, 0, 0, FFsz, b2, nullptr);

    // LN2: out = LN(H2 + X1)
    ln_kernel<<<MROWS, 256>>>(H2, X1, ln2_g, ln2_b, out);
}

// round 3
// speedup vs baseline: 2.2229x; 2.2229x over previous
#include <cuda_runtime.h>
#include <cuda_bf16.h>
#include <math.h>
#include <stdint.h>

constexpr int Bsz = 8, Ssz = 1024, Dsz = 1024, Hsz = 16, DKsz = 64, FFsz = 4096;
constexpr int MR = Bsz * Ssz;          // 8192
constexpr int NQ = 3 * Hsz * DKsz;     // 3072

typedef __nv_bfloat16 bf16;

// ---------------------------------------------------------------------------
// Static device scratch (no allocations allowed)
// ---------------------------------------------------------------------------
__device__ int   g_mask_mode;
__device__ bf16  g_Xh[(size_t)MR * Dsz],      g_Xl[(size_t)MR * Dsz];
__device__ bf16  g_Wqkvh[(size_t)NQ * Dsz],   g_Wqkvl[(size_t)NQ * Dsz];
__device__ bf16  g_FCh[(size_t)Dsz * Dsz],    g_FCl[(size_t)Dsz * Dsz];
__device__ bf16  g_W1h[(size_t)FFsz * Dsz],   g_W1l[(size_t)FFsz * Dsz];
__device__ bf16  g_W2h[(size_t)Dsz * FFsz],   g_W2l[(size_t)Dsz * FFsz];
__device__ bf16  g_QKVh[(size_t)MR * NQ],     g_QKVl[(size_t)MR * NQ];
__device__ bf16  g_Vth[(size_t)Bsz * Hsz * DKsz * Ssz], g_Vtl[(size_t)Bsz * Hsz * DKsz * Ssz];
__device__ float g_S[(size_t)Bsz * Hsz * Ssz * Ssz];
__device__ bf16  g_Ph[(size_t)Bsz * Hsz * Ssz * Ssz], g_Pl[(size_t)Bsz * Hsz * Ssz * Ssz];
__device__ bf16  g_Oh[(size_t)MR * Dsz],      g_Ol[(size_t)MR * Dsz];
__device__ float g_ATT[(size_t)MR * Dsz];
__device__ float g_X1[(size_t)MR * Dsz];
__device__ bf16  g_X1h[(size_t)MR * Dsz],     g_X1l[(size_t)MR * Dsz];
__device__ bf16  g_H1h[(size_t)MR * FFsz],    g_H1l[(size_t)MR * FFsz];
__device__ float g_H2[(size_t)MR * Dsz];

// ---------------------------------------------------------------------------
// Low-level helpers (base-ISA only: cp.async / ldmatrix / mma.sync)
// ---------------------------------------------------------------------------
__device__ __forceinline__ uint32_t smem_u32(const void* p) {
    uint32_t a;
    asm("{ .reg .u64 t; cvta.to.shared.u64 t, %1; cvt.u32.u64 %0, t; }" : "=r"(a) : "l"(p));
    return a;
}
template<int N> __device__ __forceinline__ void cp_wait() {
    asm volatile("cp.async.wait_group %0;" :: "n"(N));
}
__device__ __forceinline__ void cp16(uint32_t s, const void* g) {
    asm volatile("cp.async.cg.shared.global [%0], [%1], 16;" :: "r"(s), "l"(g));
}
__device__ __forceinline__ void cp_commit() { asm volatile("cp.async.commit_group;"); }
__device__ __forceinline__ void ldm4(uint32_t* d, uint32_t a) {
    asm volatile("ldmatrix.sync.aligned.m8n8.x4.shared.b16 {%0,%1,%2,%3}, [%4];"
                 : "=r"(d[0]), "=r"(d[1]), "=r"(d[2]), "=r"(d[3]) : "r"(a));
}
__device__ __forceinline__ void mma16816(float* c, const uint32_t* a, uint32_t b0, uint32_t b1) {
    asm volatile("mma.sync.aligned.m16n8k16.row.col.f32.bf16.bf16.f32 "
                 "{%0,%1,%2,%3}, {%4,%5,%6,%7}, {%8,%9}, {%0,%1,%2,%3};"
                 : "+f"(c[0]), "+f"(c[1]), "+f"(c[2]), "+f"(c[3])
                 : "r"(a[0]), "r"(a[1]), "r"(a[2]), "r"(a[3]), "r"(b0), "r"(b1));
}
__device__ __forceinline__ uint32_t swz(uint32_t o) { return o ^ ((o >> 3) & 0x70); }
__device__ __forceinline__ void split2(float v, bf16& h, bf16& l) {
    h = __float2bfloat16_rn(v);
    l = __float2bfloat16_rn(v - __bfloat162float(h));
}
__device__ __forceinline__ uint32_t bpack(bf16 a, bf16 b) {
    return (uint32_t)__bfloat16_as_ushort(a) | ((uint32_t)__bfloat16_as_ushort(b) << 16);
}

// ---------------------------------------------------------------------------
// fast exp (FMA pipe, avoids MUFU wall)
// ---------------------------------------------------------------------------
__device__ __forceinline__ float fast_exp(float x) {
    x = fmaxf(x, -87.0f);
    float t  = x * 1.4426950408889634f;
    float fi = floorf(t);
    float f  = t - fi;
    float p = 1.5252733e-5f;
    p = fmaf(p, f, 1.5403530e-4f);
    p = fmaf(p, f, 1.3333558e-3f);
    p = fmaf(p, f, 9.6181291e-3f);
    p = fmaf(p, f, 5.5504109e-2f);
    p = fmaf(p, f, 2.4022651e-1f);
    p = fmaf(p, f, 6.9314718e-1f);
    p = fmaf(p, f, 1.0f);
    return __int_as_float(__float_as_int(p) + ((int)fi << 23));
}

// ---------------------------------------------------------------------------
// Mask dtype detector
// ---------------------------------------------------------------------------
__global__ void detect_mask_kernel(const unsigned int* __restrict__ w) {
    __shared__ int flags[3];
    if (threadIdx.x < 3) flags[threadIdx.x] = 1;
    __syncthreads();
    int f32ok = 1, bf16ok = 1, i32ok = 1;
    for (int i = threadIdx.x; i < 1024; i += blockDim.x) {
        unsigned u = w[i];
        if (!(u == 0u || u == 0x3F800000u)) f32ok = 0;
        if (!(u == 0u || u == 0x3F800000u || u == 0x3F803F80u || u == 0x00003F80u)) bf16ok = 0;
        if (u > 1u) i32ok = 0;
    }
    if (!f32ok)  atomicAnd(&flags[0], 0);
    if (!bf16ok) atomicAnd(&flags[1], 0);
    if (!i32ok)  atomicAnd(&flags[2], 0);
    __syncthreads();
    if (threadIdx.x == 0)
        g_mask_mode = flags[0] ? 0 : (flags[1] ? 3 : (flags[2] ? 1 : 2));
}
__device__ __forceinline__ bool mask_true(const void* mask, long long off, int mode) {
    if (mode == 2) return ((const unsigned char*)mask)[off] != 0;
    if (mode == 1) return ((const int*)mask)[off] != 0;
    if (mode == 3) return ((const unsigned short*)mask)[off] != 0;
    return ((const float*)mask)[off] != 0.0f;
}

// ---------------------------------------------------------------------------
// fp32 -> hi/lo bf16 split (vectorized)
// ---------------------------------------------------------------------------
__global__ void split_kernel(const float* __restrict__ s, bf16* __restrict__ h,
                             bf16* __restrict__ l, long long n) {
    long long i = ((long long)blockIdx.x * blockDim.x + threadIdx.x) * 4;
    if (i >= n) return;
    float4 v = *(const float4*)(s + i);
    bf16 h0, l0, h1, l1, h2, l2, h3, l3;
    split2(v.x, h0, l0); split2(v.y, h1, l1);
    split2(v.z, h2, l2); split2(v.w, h3, l3);
    *(uint2*)(h + i) = make_uint2(bpack(h0, h1), bpack(h2, h3));
    *(uint2*)(l + i) = make_uint2(bpack(l0, l1), bpack(l2, l3));
}

// Pack wq|wk|wv ([H,D,64] each) into split planes [3072 rows, 1024 k]
__global__ void pack_w_split(const float* __restrict__ wq, const float* __restrict__ wk,
                             const float* __restrict__ wv) {
    long long i = (long long)blockIdx.x * blockDim.x + threadIdx.x;
    if (i >= (long long)Dsz * NQ) return;
    int d   = (int)(i % Dsz);
    int col = (int)(i / Dsz);
    int sel = col / 1024;
    int hr  = col % 1024;
    int h   = hr / 64, e = hr % 64;
    const float* w = (sel == 0) ? wq : (sel == 1) ? wk : wv;
    float v = w[((long long)h * Dsz + d) * 64 + e];
    bf16 hi, lo; split2(v, hi, lo);
    g_Wqkvh[i] = hi; g_Wqkvl[i] = lo;
}

// Transpose V planes: QKV cols [2048,3072) -> Vt [(b,h,e), s]
__global__ void vtrans_kernel() {
    __shared__ bf16 th[32][33], tl[32][33];
    int bh = blockIdx.z, b = bh >> 4, h = bh & 15;
    int s0 = blockIdx.x * 32, e0 = blockIdx.y * 32;
    int tx = threadIdx.x, ty = threadIdx.y;
    for (int i = ty; i < 32; i += 8) {
        long long src = ((long long)(b * 1024 + s0 + i)) * NQ + 2048 + h * 64 + e0 + tx;
        th[i][tx] = g_QKVh[src];
        tl[i][tx] = g_QKVl[src];
    }
    __syncthreads();
    for (int i = ty; i < 32; i += 8) {
        long long dst = ((long long)bh * 64 + e0 + i) * 1024 + s0 + tx;
        g_Vth[dst] = th[tx][i];
        g_Vtl[dst] = tl[tx][i];
    }
}

// ---------------------------------------------------------------------------
// Warp-MMA split-bf16 GEMM:  C = A @ B^T  (3 plane passes: hh, hl, lh)
//   A planes: [M, K] row-major bf16 (lda), batched (z: bb=z>>4, hh=z&15).
//   B planes: [N, K] k-contig bf16 (ldb).
//   BM=128, BK=64, 8 warps (2x4), warp tile 64 x (BN/4). cp.async dbl-buffer.
//   EPI: 0 = write hi/lo planes; 1 = mask(-125)/scale fp32 (scores);
//        2 = +bias fp32; 3 = +bias+relu -> hi/lo planes.
// ---------------------------------------------------------------------------
template<int BN, int EPI>
__global__ __launch_bounds__(256)
void mma_gemm(const bf16* __restrict__ Ah, const bf16* __restrict__ Al,
              int lda, long long sAb, long long sAh_,
              const bf16* __restrict__ Bh, const bf16* __restrict__ Bl,
              int ldb, long long sBb, long long sBh_,
              float* __restrict__ Cf, bf16* __restrict__ Ch, bf16* __restrict__ Cl,
              int ldc, long long sCb, long long sCh_,
              int K, const float* __restrict__ bias, const void* __restrict__ mask) {
    constexpr int BM  = 128;
    constexpr int WNw = BN / 4;          // per-warp n width (32 or 16)
    constexpr int NT  = WNw / 8;         // n8 tiles per warp (4 or 2)
    constexpr int NLD = WNw / 16;        // B ldmatrix.x4 per warp (2 or 1)
    constexpr int STG = (BM + BN) * 128; // stage bytes

    extern __shared__ char smem[];
    const uint32_t sb = smem_u32(smem);

    const int tid = threadIdx.x, wid = tid >> 5, lane = tid & 31;
    const int wM = wid >> 2, wN = wid & 3;
    const int g = lane >> 3, r = lane & 7;

    const int bz = blockIdx.z, bb = bz >> 4, hz = bz & 15;
    const bf16* Ahb = Ah + bb * sAb + hz * sAh_ + (long long)blockIdx.y * BM * lda;
    const bf16* Alb = Al + bb * sAb + hz * sAh_ + (long long)blockIdx.y * BM * lda;
    const int n0 = blockIdx.x * BN;
    const bf16* Bhb = Bh + bb * sBb + hz * sBh_ + (long long)n0 * ldb;
    const bf16* Blb = Bl + bb * sBb + hz * sBh_ + (long long)n0 * ldb;

    const int KC = K >> 6, NIT = 3 * KC;

    float acc[4][NT][4];
#pragma unroll
    for (int a = 0; a < 4; a++)
#pragma unroll
        for (int b = 0; b < NT; b++)
#pragma unroll
            for (int c = 0; c < 4; c++) acc[a][b][c] = 0.0f;

    auto issue = [&](int i, int buf) {
        int pass = i / KC;
        int k0 = (i - pass * KC) << 6;
        const bf16* Ap = (pass == 2) ? Alb : Ahb;
        const bf16* Bp = (pass == 1) ? Blb : Bhb;
        uint32_t aD = sb + buf * STG, bD = aD + BM * 128;
#pragma unroll
        for (int w = 0; w < 4; w++) {
            int idx = w * 256 + tid, row = idx >> 3, seg = idx & 7;
            cp16(aD + swz(row * 128 + seg * 16), Ap + (long long)row * lda + k0 + seg * 8);
        }
#pragma unroll
        for (int w = 0; w < BN / 32; w++) {
            int idx = w * 256 + tid, row = idx >> 3, seg = idx & 7;
            cp16(bD + swz(row * 128 + seg * 16), Bp + (long long)row * ldb + k0 + seg * 8);
        }
        cp_commit();
    };

    issue(0, 0);
    for (int i = 0; i < NIT; i++) {
        if (i + 1 < NIT) { issue(i + 1, (i + 1) & 1); cp_wait<1>(); }
        else             { cp_wait<0>(); }
        __syncthreads();
        uint32_t aT = sb + (i & 1) * STG, bT = aT + BM * 128;
#pragma unroll
        for (int ks = 0; ks < 4; ks++) {
            uint32_t af[4][4];
#pragma unroll
            for (int mt = 0; mt < 4; mt++) {
                int rw = wM * 64 + mt * 16 + (g & 1) * 8 + r;
                ldm4(af[mt], aT + swz((uint32_t)(rw * 128 + ks * 32 + (g >> 1) * 16)));
            }
            uint32_t bfr[NLD][4];
#pragma unroll
            for (int nl = 0; nl < NLD; nl++) {
                int rw = wN * WNw + nl * 16 + (g >> 1) * 8 + r;
                ldm4(bfr[nl], bT + swz((uint32_t)(rw * 128 + ks * 32 + (g & 1) * 16)));
            }
#pragma unroll
            for (int mt = 0; mt < 4; mt++)
#pragma unroll
                for (int j = 0; j < NT; j++)
                    mma16816(acc[mt][j], af[mt], bfr[j >> 1][(j & 1) * 2], bfr[j >> 1][(j & 1) * 2 + 1]);
        }
        __syncthreads();
    }

    // ---- epilogue ----
    const int rb  = blockIdx.y * BM + wM * 64;
    const int cb0 = n0 + wN * WNw;
    float* Cfb = (EPI == 1 || EPI == 2) ? (Cf + bb * sCb + hz * sCh_) : nullptr;
    bf16*  Chb = (EPI == 0 || EPI == 3) ? (Ch + bb * sCb + hz * sCh_) : nullptr;
    bf16*  Clb = (EPI == 0 || EPI == 3) ? (Cl + bb * sCb + hz * sCh_) : nullptr;
    const int mmode = (EPI == 1) ? g_mask_mode : 0;

#pragma unroll
    for (int mt = 0; mt < 4; mt++)
#pragma unroll
        for (int j = 0; j < NT; j++) {
            int row0 = rb + mt * 16 + (lane >> 2);
            int col  = cb0 + j * 8 + (lane & 3) * 2;
#pragma unroll
            for (int h2 = 0; h2 < 2; h2++) {
                int row = row0 + h2 * 8;
                float v0 = acc[mt][j][h2 * 2 + 0];
                float v1 = acc[mt][j][h2 * 2 + 1];
                if (EPI == 2 || EPI == 3) { v0 += bias[col]; v1 += bias[col + 1]; }
                if (EPI == 3) { v0 = fmaxf(v0, 0.0f); v1 = fmaxf(v1, 0.0f); }
                if (EPI == 1) {
                    long long mb = (long long)bb * Ssz * Ssz + (long long)row * Ssz;
                    v0 = mask_true(mask, mb + col,     mmode) ? v0 * 0.125f : -125.0f;
                    v1 = mask_true(mask, mb + col + 1, mmode) ? v1 * 0.125f : -125.0f;
                }
                long long co = (long long)row * ldc + col;
                if (EPI == 1 || EPI == 2) {
                    *(float2*)(Cfb + co) = make_float2(v0, v1);
                } else {
                    bf16 h0, l0, h1, l1;
                    split2(v0, h0, l0); split2(v1, h1, l1);
                    *(uint32_t*)(Chb + co) = bpack(h0, h1);
                    *(uint32_t*)(Clb + co) = bpack(l0, l1);
                }
            }
        }
}

// ---------------------------------------------------------------------------
// Column softmax over the QUERY axis; reads fp32 S, writes hi/lo P planes
// ---------------------------------------------------------------------------
__global__ __launch_bounds__(256)
void col_softmax_kernel(const float* __restrict__ S, bf16* __restrict__ Ph,
                        bf16* __restrict__ Pl) {
    const int c = threadIdx.x & 63;
    const int r = threadIdx.x >> 6;
    const long long zoff = (long long)blockIdx.y * ((long long)Ssz * Ssz);
    const int coff = blockIdx.x * 64 + c;
    const float* base = S + zoff + coff;

    float m = -3.0e38f, l = 0.0f;
    for (int q = r; q < Ssz; q += 4) {
        float v = base[(long long)q * Ssz];
        float mn = fmaxf(m, v);
        l = l * fast_exp(m - mn) + fast_exp(v - mn);
        m = mn;
    }
    __shared__ float sm[4][64], sl[4][64];
    sm[r][c] = m; sl[r][c] = l;
    __syncthreads();
    if (r == 0) {
        float M = m, L = l;
#pragma unroll
        for (int i = 1; i < 4; i++) {
            float m2 = sm[i][c], l2 = sl[i][c];
            float mn = fmaxf(M, m2);
            L = L * fast_exp(M - mn) + l2 * fast_exp(m2 - mn);
            M = mn;
        }
        sm[0][c] = M;
        sl[0][c] = 1.0f / L;
    }
    __syncthreads();
    const float M = sm[0][c];
    const float inv = sl[0][c];
    for (int q = r; q < Ssz; q += 4) {
        long long off = zoff + (long long)q * Ssz + coff;
        float p = fast_exp(base[(long long)q * Ssz] - M) * inv;
        bf16 ph, pl; split2(p, ph, pl);
        Ph[off] = ph; Pl[off] = pl;
    }
}

// ---------------------------------------------------------------------------
// Fused residual-add + LayerNorm; optional hi/lo plane emission
// ---------------------------------------------------------------------------
template<bool PL>
__global__ __launch_bounds__(256)
void ln_kernel(const float* __restrict__ a, const float* __restrict__ b,
               const float* __restrict__ g, const float* __restrict__ beta,
               float* __restrict__ out, bf16* __restrict__ oh, bf16* __restrict__ ol) {
    const int t = threadIdx.x;
    const long long base = (long long)blockIdx.x * Dsz;
    float v[4];
    float s = 0.0f;
#pragma unroll
    for (int j = 0; j < 4; j++) {
        int idx = t + j * 256;
        v[j] = a[base + idx] + b[base + idx];
        s += v[j];
    }
    __shared__ float red[8];
    __shared__ float bc, bc2;
#pragma unroll
    for (int o = 16; o; o >>= 1) s += __shfl_xor_sync(0xffffffffu, s, o);
    if ((t & 31) == 0) red[t >> 5] = s;
    __syncthreads();
    if (t == 0) {
        float tt = 0;
#pragma unroll
        for (int i = 0; i < 8; i++) tt += red[i];
        bc = tt * (1.0f / 1024.0f);
    }
    __syncthreads();
    const float mu = bc;
    float q = 0.0f;
#pragma unroll
    for (int j = 0; j < 4; j++) { float d = v[j] - mu; q += d * d; }
    __syncthreads();
#pragma unroll
    for (int o = 16; o; o >>= 1) q += __shfl_xor_sync(0xffffffffu, q, o);
    if ((t & 31) == 0) red[t >> 5] = q;
    __syncthreads();
    if (t == 0) {
        float tt = 0;
#pragma unroll
        for (int i = 0; i < 8; i++) tt += red[i];
        bc2 = rsqrtf(tt * (1.0f / 1024.0f) + 1e-5f);
    }
    __syncthreads();
    const float rs = bc2;
#pragma unroll
    for (int j = 0; j < 4; j++) {
        int idx = t + j * 256;
        float o = (v[j] - mu) * rs * g[idx] + beta[idx];
        out[base + idx] = o;
        if (PL) {
            bf16 h, l; split2(o, h, l);
            oh[base + idx] = h; ol[base + idx] = l;
        }
    }
}

// ---------------------------------------------------------------------------
// Launch
// ---------------------------------------------------------------------------
extern "C" void kernel_launch(void* const* d_in, const int* in_sizes, int n_in,
                              void* d_out, int out_size) {
    const float* x     = (const float*)d_in[0];
    const void*  mask  = d_in[1];
    const float* wq    = (const float*)d_in[2];
    const float* wk    = (const float*)d_in[3];
    const float* wv    = (const float*)d_in[4];
    const float* fc_w  = (const float*)d_in[5];
    const float* fc_b  = (const float*)d_in[6];
    const float* w1    = (const float*)d_in[7];
    const float* b1    = (const float*)d_in[8];
    const float* w2    = (const float*)d_in[9];
    const float* b2    = (const float*)d_in[10];
    const float* ln1_g = (const float*)d_in[11];
    const float* ln1_b = (const float*)d_in[12];
    const float* ln2_g = (const float*)d_in[13];
    const float* ln2_b = (const float*)d_in[14];
    float* out = (float*)d_out;

    bf16 *Xh, *Xl, *Wqh, *Wql, *FCh, *FCl, *W1h, *W1l, *W2h, *W2l;
    bf16 *QKVh, *QKVl, *Vth, *Vtl, *Ph, *Pl, *Oh, *Ol, *X1h, *X1l, *H1h, *H1l;
    float *S, *ATT, *X1, *H2;
    cudaGetSymbolAddress((void**)&Xh, g_Xh);     cudaGetSymbolAddress((void**)&Xl, g_Xl);
    cudaGetSymbolAddress((void**)&Wqh, g_Wqkvh); cudaGetSymbolAddress((void**)&Wql, g_Wqkvl);
    cudaGetSymbolAddress((void**)&FCh, g_FCh);   cudaGetSymbolAddress((void**)&FCl, g_FCl);
    cudaGetSymbolAddress((void**)&W1h, g_W1h);   cudaGetSymbolAddress((void**)&W1l, g_W1l);
    cudaGetSymbolAddress((void**)&W2h, g_W2h);   cudaGetSymbolAddress((void**)&W2l, g_W2l);
    cudaGetSymbolAddress((void**)&QKVh, g_QKVh); cudaGetSymbolAddress((void**)&QKVl, g_QKVl);
    cudaGetSymbolAddress((void**)&Vth, g_Vth);   cudaGetSymbolAddress((void**)&Vtl, g_Vtl);
    cudaGetSymbolAddress((void**)&S, g_S);
    cudaGetSymbolAddress((void**)&Ph, g_Ph);     cudaGetSymbolAddress((void**)&Pl, g_Pl);
    cudaGetSymbolAddress((void**)&Oh, g_Oh);     cudaGetSymbolAddress((void**)&Ol, g_Ol);
    cudaGetSymbolAddress((void**)&ATT, g_ATT);
    cudaGetSymbolAddress((void**)&X1, g_X1);
    cudaGetSymbolAddress((void**)&X1h, g_X1h);   cudaGetSymbolAddress((void**)&X1l, g_X1l);
    cudaGetSymbolAddress((void**)&H1h, g_H1h);   cudaGetSymbolAddress((void**)&H1l, g_H1l);
    cudaGetSymbolAddress((void**)&H2, g_H2);

    constexpr int SM128 = 2 * (128 + 128) * 128;   // 65536
    constexpr int SM64  = 2 * (128 + 64) * 128;    // 49152
    cudaFuncSetAttribute(mma_gemm<128, 0>, cudaFuncAttributeMaxDynamicSharedMemorySize, SM128);
    cudaFuncSetAttribute(mma_gemm<128, 1>, cudaFuncAttributeMaxDynamicSharedMemorySize, SM128);
    cudaFuncSetAttribute(mma_gemm<128, 2>, cudaFuncAttributeMaxDynamicSharedMemorySize, SM128);
    cudaFuncSetAttribute(mma_gemm<128, 3>, cudaFuncAttributeMaxDynamicSharedMemorySize, SM128);
    cudaFuncSetAttribute(mma_gemm<64, 0>,  cudaFuncAttributeMaxDynamicSharedMemorySize, SM64);

    detect_mask_kernel<<<1, 256>>>((const unsigned int*)mask);

    // Input / weight splits
    split_kernel<<<(MR * Dsz / 4 + 255) / 256, 256>>>(x, Xh, Xl, (long long)MR * Dsz);
    pack_w_split<<<((long long)Dsz * NQ + 255) / 256, 256>>>(wq, wk, wv);
    split_kernel<<<((long long)Dsz * Dsz / 4 + 255) / 256, 256>>>(fc_w, FCh, FCl, (long long)Dsz * Dsz);
    split_kernel<<<((long long)FFsz * Dsz / 4 + 255) / 256, 256>>>(w1, W1h, W1l, (long long)FFsz * Dsz);
    split_kernel<<<((long long)Dsz * FFsz / 4 + 255) / 256, 256>>>(w2, W2h, W2l, (long long)Dsz * FFsz);

    // G1: QKV planes = X @ Wqkv^T
    mma_gemm<128, 0><<<dim3(NQ / 128, MR / 128, 1), 256, SM128>>>(
        Xh, Xl, Dsz, 0, 0, Wqh, Wql, Dsz, 0, 0,
        nullptr, QKVh, QKVl, NQ, 0, 0, Dsz, nullptr, nullptr);

    // V transpose into Vt planes
    vtrans_kernel<<<dim3(32, 2, 128), dim3(32, 8)>>>();

    // G2: S = Q @ K^T per (b,h), epilogue mask(-125) + *0.125 -> fp32
    mma_gemm<128, 1><<<dim3(Ssz / 128, Ssz / 128, Bsz * Hsz), 256, SM128>>>(
        QKVh, QKVl, NQ, (long long)Ssz * NQ, 64,
        QKVh + 1024, QKVl + 1024, NQ, (long long)Ssz * NQ, 64,
        S, nullptr, nullptr, Ssz, (long long)Hsz * Ssz * Ssz, (long long)Ssz * Ssz,
        DKsz, nullptr, mask);

    // Column softmax -> P planes
    col_softmax_kernel<<<dim3(Ssz / 64, Bsz * Hsz), 256>>>(S, Ph, Pl);

    // G3: O planes = P @ Vt^T per (b,h)
    mma_gemm<64, 0><<<dim3(1, Ssz / 128, Bsz * Hsz), 256, SM64>>>(
        Ph, Pl, Ssz, (long long)Hsz * Ssz * Ssz, (long long)Ssz * Ssz,
        Vth, Vtl, Ssz, (long long)Hsz * DKsz * Ssz, (long long)DKsz * Ssz,
        nullptr, Oh, Ol, Dsz, (long long)Ssz * Dsz, 64,
        Ssz, nullptr, nullptr);

    // G4: ATT = O @ fc_w^T + fc_b (fp32)
    mma_gemm<128, 2><<<dim3(Dsz / 128, MR / 128, 1), 256, SM128>>>(
        Oh, Ol, Dsz, 0, 0, FCh, FCl, Dsz, 0, 0,
        ATT, nullptr, nullptr, Dsz, 0, 0, Dsz, fc_b, nullptr);

    // LN1 -> X1 fp32 + planes
    ln_kernel<true><<<MR, 256>>>(ATT, x, ln1_g, ln1_b, X1, X1h, X1l);

    // G5: H1 planes = relu(X1 @ w1^T + b1)
    mma_gemm<128, 3><<<dim3(FFsz / 128, MR / 128, 1), 256, SM128>>>(
        X1h, X1l, Dsz, 0, 0, W1h, W1l, Dsz, 0, 0,
        nullptr, H1h, H1l, FFsz, 0, 0, Dsz, b1, nullptr);

    // G6: H2 = H1 @ w2^T + b2 (fp32)
    mma_gemm<128, 2><<<dim3(Dsz / 128, MR / 128, 1), 256, SM128>>>(
        H1h, H1l, FFsz, 0, 0, W2h, W2l, FFsz, 0, 0,
        H2, nullptr, nullptr, Dsz, 0, 0, FFsz, b2, nullptr);

    // LN2 -> out
    ln_kernel<false><<<MR, 256>>>(H2, X1, ln2_g, ln2_b, out, nullptr, nullptr);
}

// round 4
// speedup vs baseline: 2.6779x; 1.2047x over previous
#include <cuda_runtime.h>
#include <cuda_bf16.h>
#include <math.h>
#include <stdint.h>

constexpr int Bsz = 8, Ssz = 1024, Dsz = 1024, Hsz = 16, DKsz = 64, FFsz = 4096;
constexpr int MR = Bsz * Ssz;          // 8192
constexpr int NQ = 3 * Hsz * DKsz;     // 3072

typedef __nv_bfloat16 bf16;

// ---------------------------------------------------------------------------
// Static device scratch (no allocations allowed)
// ---------------------------------------------------------------------------
__device__ int   g_mask_mode;
__device__ bf16  g_Xh[(size_t)MR * Dsz],      g_Xl[(size_t)MR * Dsz];
__device__ bf16  g_Wqkvh[(size_t)NQ * Dsz],   g_Wqkvl[(size_t)NQ * Dsz];
__device__ bf16  g_FCh[(size_t)Dsz * Dsz],    g_FCl[(size_t)Dsz * Dsz];
__device__ bf16  g_W1h[(size_t)FFsz * Dsz],   g_W1l[(size_t)FFsz * Dsz];
__device__ bf16  g_W2h[(size_t)Dsz * FFsz],   g_W2l[(size_t)Dsz * FFsz];
__device__ bf16  g_QKVh[(size_t)MR * NQ],     g_QKVl[(size_t)MR * NQ];
__device__ bf16  g_Vth[(size_t)Bsz * Hsz * DKsz * Ssz], g_Vtl[(size_t)Bsz * Hsz * DKsz * Ssz];
__device__ float g_S[(size_t)Bsz * Hsz * Ssz * Ssz];
__device__ bf16  g_Ph[(size_t)Bsz * Hsz * Ssz * Ssz], g_Pl[(size_t)Bsz * Hsz * Ssz * Ssz];
__device__ bf16  g_Oh[(size_t)MR * Dsz],      g_Ol[(size_t)MR * Dsz];
__device__ float g_ATT[(size_t)MR * Dsz];
__device__ float g_X1[(size_t)MR * Dsz];
__device__ bf16  g_X1h[(size_t)MR * Dsz],     g_X1l[(size_t)MR * Dsz];
__device__ bf16  g_H1h[(size_t)MR * FFsz],    g_H1l[(size_t)MR * FFsz];
__device__ float g_H2[(size_t)MR * Dsz];

// ---------------------------------------------------------------------------
// Low-level helpers (base-ISA only: cp.async / ldmatrix / mma.sync)
// ---------------------------------------------------------------------------
__device__ __forceinline__ uint32_t smem_u32(const void* p) {
    uint32_t a;
    asm("{ .reg .u64 t; cvta.to.shared.u64 t, %1; cvt.u32.u64 %0, t; }" : "=r"(a) : "l"(p));
    return a;
}
template<int N> __device__ __forceinline__ void cp_wait() {
    asm volatile("cp.async.wait_group %0;" :: "n"(N));
}
__device__ __forceinline__ void cp16(uint32_t s, const void* g) {
    asm volatile("cp.async.cg.shared.global [%0], [%1], 16;" :: "r"(s), "l"(g));
}
__device__ __forceinline__ void cp_commit() { asm volatile("cp.async.commit_group;"); }
__device__ __forceinline__ void ldm4(uint32_t* d, uint32_t a) {
    asm volatile("ldmatrix.sync.aligned.m8n8.x4.shared.b16 {%0,%1,%2,%3}, [%4];"
                 : "=r"(d[0]), "=r"(d[1]), "=r"(d[2]), "=r"(d[3]) : "r"(a));
}
__device__ __forceinline__ void mma16816(float* c, const uint32_t* a, uint32_t b0, uint32_t b1) {
    asm volatile("mma.sync.aligned.m16n8k16.row.col.f32.bf16.bf16.f32 "
                 "{%0,%1,%2,%3}, {%4,%5,%6,%7}, {%8,%9}, {%0,%1,%2,%3};"
                 : "+f"(c[0]), "+f"(c[1]), "+f"(c[2]), "+f"(c[3])
                 : "r"(a[0]), "r"(a[1]), "r"(a[2]), "r"(a[3]), "r"(b0), "r"(b1));
}
__device__ __forceinline__ uint32_t swz(uint32_t o) { return o ^ ((o >> 3) & 0x70); }
__device__ __forceinline__ void split2(float v, bf16& h, bf16& l) {
    h = __float2bfloat16_rn(v);
    l = __float2bfloat16_rn(v - __bfloat162float(h));
}
__device__ __forceinline__ uint32_t bpack(bf16 a, bf16 b) {
    return (uint32_t)__bfloat16_as_ushort(a) | ((uint32_t)__bfloat16_as_ushort(b) << 16);
}

// ---------------------------------------------------------------------------
// fast exp (FMA pipe, avoids MUFU wall)
// ---------------------------------------------------------------------------
__device__ __forceinline__ float fast_exp(float x) {
    x = fmaxf(x, -87.0f);
    float t  = x * 1.4426950408889634f;
    float fi = floorf(t);
    float f  = t - fi;
    float p = 1.5252733e-5f;
    p = fmaf(p, f, 1.5403530e-4f);
    p = fmaf(p, f, 1.3333558e-3f);
    p = fmaf(p, f, 9.6181291e-3f);
    p = fmaf(p, f, 5.5504109e-2f);
    p = fmaf(p, f, 2.4022651e-1f);
    p = fmaf(p, f, 6.9314718e-1f);
    p = fmaf(p, f, 1.0f);
    return __int_as_float(__float_as_int(p) + ((int)fi << 23));
}

// ---------------------------------------------------------------------------
// Mask dtype detector
// ---------------------------------------------------------------------------
__global__ void detect_mask_kernel(const unsigned int* __restrict__ w) {
    __shared__ int flags[3];
    if (threadIdx.x < 3) flags[threadIdx.x] = 1;
    __syncthreads();
    int f32ok = 1, bf16ok = 1, i32ok = 1;
    for (int i = threadIdx.x; i < 1024; i += blockDim.x) {
        unsigned u = w[i];
        if (!(u == 0u || u == 0x3F800000u)) f32ok = 0;
        if (!(u == 0u || u == 0x3F800000u || u == 0x3F803F80u || u == 0x00003F80u)) bf16ok = 0;
        if (u > 1u) i32ok = 0;
    }
    if (!f32ok)  atomicAnd(&flags[0], 0);
    if (!bf16ok) atomicAnd(&flags[1], 0);
    if (!i32ok)  atomicAnd(&flags[2], 0);
    __syncthreads();
    if (threadIdx.x == 0)
        g_mask_mode = flags[0] ? 0 : (flags[1] ? 3 : (flags[2] ? 1 : 2));
}
__device__ __forceinline__ bool mask_true(const void* mask, long long off, int mode) {
    if (mode == 2) return ((const unsigned char*)mask)[off] != 0;
    if (mode == 1) return ((const int*)mask)[off] != 0;
    if (mode == 3) return ((const unsigned short*)mask)[off] != 0;
    return ((const float*)mask)[off] != 0.0f;
}

// ---------------------------------------------------------------------------
// fp32 -> hi/lo bf16 split (vectorized)
// ---------------------------------------------------------------------------
__global__ void split_kernel(const float* __restrict__ s, bf16* __restrict__ h,
                             bf16* __restrict__ l, long long n) {
    long long i = ((long long)blockIdx.x * blockDim.x + threadIdx.x) * 4;
    if (i >= n) return;
    float4 v = *(const float4*)(s + i);
    bf16 h0, l0, h1, l1, h2, l2, h3, l3;
    split2(v.x, h0, l0); split2(v.y, h1, l1);
    split2(v.z, h2, l2); split2(v.w, h3, l3);
    *(uint2*)(h + i) = make_uint2(bpack(h0, h1), bpack(h2, h3));
    *(uint2*)(l + i) = make_uint2(bpack(l0, l1), bpack(l2, l3));
}

// Pack wq|wk|wv ([H,D,64] each) into split planes [3072 rows, 1024 k]
__global__ void pack_w_split(const float* __restrict__ wq, const float* __restrict__ wk,
                             const float* __restrict__ wv) {
    long long i = (long long)blockIdx.x * blockDim.x + threadIdx.x;
    if (i >= (long long)Dsz * NQ) return;
    int d   = (int)(i % Dsz);
    int col = (int)(i / Dsz);
    int sel = col / 1024;
    int hr  = col % 1024;
    int h   = hr / 64, e = hr % 64;
    const float* w = (sel == 0) ? wq : (sel == 1) ? wk : wv;
    float v = w[((long long)h * Dsz + d) * 64 + e];
    bf16 hi, lo; split2(v, hi, lo);
    g_Wqkvh[i] = hi; g_Wqkvl[i] = lo;
}

// Transpose V planes: QKV cols [2048,3072) -> Vt [(b,h,e), s]
__global__ void vtrans_kernel() {
    __shared__ bf16 th[32][33], tl[32][33];
    int bh = blockIdx.z, b = bh >> 4, h = bh & 15;
    int s0 = blockIdx.x * 32, e0 = blockIdx.y * 32;
    int tx = threadIdx.x, ty = threadIdx.y;
    for (int i = ty; i < 32; i += 8) {
        long long src = ((long long)(b * 1024 + s0 + i)) * NQ + 2048 + h * 64 + e0 + tx;
        th[i][tx] = g_QKVh[src];
        tl[i][tx] = g_QKVl[src];
    }
    __syncthreads();
    for (int i = ty; i < 32; i += 8) {
        long long dst = ((long long)bh * 64 + e0 + i) * 1024 + s0 + tx;
        g_Vth[dst] = th[tx][i];
        g_Vtl[dst] = tl[tx][i];
    }
}

// ---------------------------------------------------------------------------
// Warp-MMA split-bf16 GEMM:  C = A @ B^T.
//   Per k-chunk: load 4 planes (Ah, Al, Bh, Bl) ONCE, then issue 3 MMA passes
//   (Ah*Bh + Ah*Bl + Al*Bh) against them. 33% less load traffic vs 3 sweeps.
//   A planes: [M, K] row-major bf16 (lda), batched (z: bb=z>>4, hh=z&15).
//   B planes: [N, K] k-contig bf16 (ldb).
//   BM=128, BK=64, 8 warps (2x4), warp tile 64 x (BN/4). cp.async dbl-buffer.
//   EPI: 0 = write hi/lo planes; 1 = mask(-125)/scale fp32 (scores);
//        2 = +bias fp32; 3 = +bias+relu -> hi/lo planes.
// ---------------------------------------------------------------------------
template<int BN, int EPI>
__global__ __launch_bounds__(256)
void mma_gemm(const bf16* __restrict__ Ah, const bf16* __restrict__ Al,
              int lda, long long sAb, long long sAh_,
              const bf16* __restrict__ Bh, const bf16* __restrict__ Bl,
              int ldb, long long sBb, long long sBh_,
              float* __restrict__ Cf, bf16* __restrict__ Ch, bf16* __restrict__ Cl,
              int ldc, long long sCb, long long sCh_,
              int K, const float* __restrict__ bias, const void* __restrict__ mask) {
    constexpr int BM  = 128;
    constexpr int WNw = BN / 4;              // per-warp n width (32 or 16)
    constexpr int NT  = WNw / 8;             // n8 tiles per warp (4 or 2)
    constexpr int NLD = WNw / 16;            // B ldmatrix.x4 per warp (2 or 1)
    constexpr int ATB = BM * 128;            // one A plane tile bytes (16 KB)
    constexpr int BTB = BN * 128;            // one B plane tile bytes
    constexpr int STG = 2 * ATB + 2 * BTB;   // stage bytes (4 planes)

    extern __shared__ char smem[];
    const uint32_t sb = smem_u32(smem);

    const int tid = threadIdx.x, wid = tid >> 5, lane = tid & 31;
    const int wM = wid >> 2, wN = wid & 3;
    const int g = lane >> 3, r = lane & 7;

    const int bz = blockIdx.z, bb = bz >> 4, hz = bz & 15;
    const bf16* Ahb = Ah + bb * sAb + hz * sAh_ + (long long)blockIdx.y * BM * lda;
    const bf16* Alb = Al + bb * sAb + hz * sAh_ + (long long)blockIdx.y * BM * lda;
    const int n0 = blockIdx.x * BN;
    const bf16* Bhb = Bh + bb * sBb + hz * sBh_ + (long long)n0 * ldb;
    const bf16* Blb = Bl + bb * sBb + hz * sBh_ + (long long)n0 * ldb;

    const int KC = K >> 6;

    float acc[4][NT][4];
#pragma unroll
    for (int a = 0; a < 4; a++)
#pragma unroll
        for (int b = 0; b < NT; b++)
#pragma unroll
            for (int c = 0; c < 4; c++) acc[a][b][c] = 0.0f;

    auto issue = [&](int kc, int buf) {
        int k0 = kc << 6;
        uint32_t aH = sb + buf * STG;
        uint32_t aL = aH + ATB;
        uint32_t bH = aL + ATB;
        uint32_t bL = bH + BTB;
#pragma unroll
        for (int w = 0; w < 4; w++) {
            int idx = w * 256 + tid, row = idx >> 3, seg = idx & 7;
            uint32_t so = swz(row * 128 + seg * 16);
            long long go = (long long)row * lda + k0 + seg * 8;
            cp16(aH + so, Ahb + go);
            cp16(aL + so, Alb + go);
        }
#pragma unroll
        for (int w = 0; w < BN / 32; w++) {
            int idx = w * 256 + tid, row = idx >> 3, seg = idx & 7;
            uint32_t so = swz(row * 128 + seg * 16);
            long long go = (long long)row * ldb + k0 + seg * 8;
            cp16(bH + so, Bhb + go);
            cp16(bL + so, Blb + go);
        }
        cp_commit();
    };

    issue(0, 0);
    for (int kc = 0; kc < KC; kc++) {
        if (kc + 1 < KC) { issue(kc + 1, (kc + 1) & 1); cp_wait<1>(); }
        else             { cp_wait<0>(); }
        __syncthreads();
        const uint32_t aH = sb + (kc & 1) * STG;
        const uint32_t aL = aH + ATB;
        const uint32_t bH = aL + ATB;
        const uint32_t bL = bH + BTB;
#pragma unroll
        for (int ks = 0; ks < 4; ks++) {
            uint32_t ahf[4][4], alf[4][4];
#pragma unroll
            for (int mt = 0; mt < 4; mt++) {
                int rw = wM * 64 + mt * 16 + (g & 1) * 8 + r;
                uint32_t so = swz((uint32_t)(rw * 128 + ks * 32 + (g >> 1) * 16));
                ldm4(ahf[mt], aH + so);
                ldm4(alf[mt], aL + so);
            }
            uint32_t bhf[NLD][4], blf[NLD][4];
#pragma unroll
            for (int nl = 0; nl < NLD; nl++) {
                int rw = wN * WNw + nl * 16 + (g >> 1) * 8 + r;
                uint32_t so = swz((uint32_t)(rw * 128 + ks * 32 + (g & 1) * 16));
                ldm4(bhf[nl], bH + so);
                ldm4(blf[nl], bL + so);
            }
#pragma unroll
            for (int mt = 0; mt < 4; mt++)
#pragma unroll
                for (int j = 0; j < NT; j++)
                    mma16816(acc[mt][j], ahf[mt], bhf[j >> 1][(j & 1) * 2], bhf[j >> 1][(j & 1) * 2 + 1]);
#pragma unroll
            for (int mt = 0; mt < 4; mt++)
#pragma unroll
                for (int j = 0; j < NT; j++)
                    mma16816(acc[mt][j], ahf[mt], blf[j >> 1][(j & 1) * 2], blf[j >> 1][(j & 1) * 2 + 1]);
#pragma unroll
            for (int mt = 0; mt < 4; mt++)
#pragma unroll
                for (int j = 0; j < NT; j++)
                    mma16816(acc[mt][j], alf[mt], bhf[j >> 1][(j & 1) * 2], bhf[j >> 1][(j & 1) * 2 + 1]);
        }
        __syncthreads();
    }

    // ---- epilogue ----
    const int rb  = blockIdx.y * BM + wM * 64;
    const int cb0 = n0 + wN * WNw;
    float* Cfb = (EPI == 1 || EPI == 2) ? (Cf + bb * sCb + hz * sCh_) : nullptr;
    bf16*  Chb = (EPI == 0 || EPI == 3) ? (Ch + bb * sCb + hz * sCh_) : nullptr;
    bf16*  Clb = (EPI == 0 || EPI == 3) ? (Cl + bb * sCb + hz * sCh_) : nullptr;
    const int mmode = (EPI == 1) ? g_mask_mode : 0;

#pragma unroll
    for (int mt = 0; mt < 4; mt++)
#pragma unroll
        for (int j = 0; j < NT; j++) {
            int row0 = rb + mt * 16 + (lane >> 2);
            int col  = cb0 + j * 8 + (lane & 3) * 2;
#pragma unroll
            for (int h2 = 0; h2 < 2; h2++) {
                int row = row0 + h2 * 8;
                float v0 = acc[mt][j][h2 * 2 + 0];
                float v1 = acc[mt][j][h2 * 2 + 1];
                if (EPI == 2 || EPI == 3) { v0 += bias[col]; v1 += bias[col + 1]; }
                if (EPI == 3) { v0 = fmaxf(v0, 0.0f); v1 = fmaxf(v1, 0.0f); }
                if (EPI == 1) {
                    long long mb = (long long)bb * Ssz * Ssz + (long long)row * Ssz;
                    v0 = mask_true(mask, mb + col,     mmode) ? v0 * 0.125f : -125.0f;
                    v1 = mask_true(mask, mb + col + 1, mmode) ? v1 * 0.125f : -125.0f;
                }
                long long co = (long long)row * ldc + col;
                if (EPI == 1 || EPI == 2) {
                    *(float2*)(Cfb + co) = make_float2(v0, v1);
                } else {
                    bf16 h0, l0, h1, l1;
                    split2(v0, h0, l0); split2(v1, h1, l1);
                    *(uint32_t*)(Chb + co) = bpack(h0, h1);
                    *(uint32_t*)(Clb + co) = bpack(l0, l1);
                }
            }
        }
}

// ---------------------------------------------------------------------------
// Column softmax over the QUERY axis; reads fp32 S, writes hi/lo P planes
// ---------------------------------------------------------------------------
__global__ __launch_bounds__(256)
void col_softmax_kernel(const float* __restrict__ S, bf16* __restrict__ Ph,
                        bf16* __restrict__ Pl) {
    const int c = threadIdx.x & 63;
    const int r = threadIdx.x >> 6;
    const long long zoff = (long long)blockIdx.y * ((long long)Ssz * Ssz);
    const int coff = blockIdx.x * 64 + c;
    const float* base = S + zoff + coff;

    float m = -3.0e38f, l = 0.0f;
    for (int q = r; q < Ssz; q += 4) {
        float v = base[(long long)q * Ssz];
        float mn = fmaxf(m, v);
        l = l * fast_exp(m - mn) + fast_exp(v - mn);
        m = mn;
    }
    __shared__ float sm[4][64], sl[4][64];
    sm[r][c] = m; sl[r][c] = l;
    __syncthreads();
    if (r == 0) {
        float M = m, L = l;
#pragma unroll
        for (int i = 1; i < 4; i++) {
            float m2 = sm[i][c], l2 = sl[i][c];
            float mn = fmaxf(M, m2);
            L = L * fast_exp(M - mn) + l2 * fast_exp(m2 - mn);
            M = mn;
        }
        sm[0][c] = M;
        sl[0][c] = 1.0f / L;
    }
    __syncthreads();
    const float M = sm[0][c];
    const float inv = sl[0][c];
    for (int q = r; q < Ssz; q += 4) {
        long long off = zoff + (long long)q * Ssz + coff;
        float p = fast_exp(base[(long long)q * Ssz] - M) * inv;
        bf16 ph, pl; split2(p, ph, pl);
        Ph[off] = ph; Pl[off] = pl;
    }
}

// ---------------------------------------------------------------------------
// Fused residual-add + LayerNorm; optional hi/lo plane emission
// ---------------------------------------------------------------------------
template<bool PL>
__global__ __launch_bounds__(256)
void ln_kernel(const float* __restrict__ a, const float* __restrict__ b,
               const float* __restrict__ g, const float* __restrict__ beta,
               float* __restrict__ out, bf16* __restrict__ oh, bf16* __restrict__ ol) {
    const int t = threadIdx.x;
    const long long base = (long long)blockIdx.x * Dsz;
    float v[4];
    float s = 0.0f;
#pragma unroll
    for (int j = 0; j < 4; j++) {
        int idx = t + j * 256;
        v[j] = a[base + idx] + b[base + idx];
        s += v[j];
    }
    __shared__ float red[8];
    __shared__ float bc, bc2;
#pragma unroll
    for (int o = 16; o; o >>= 1) s += __shfl_xor_sync(0xffffffffu, s, o);
    if ((t & 31) == 0) red[t >> 5] = s;
    __syncthreads();
    if (t == 0) {
        float tt = 0;
#pragma unroll
        for (int i = 0; i < 8; i++) tt += red[i];
        bc = tt * (1.0f / 1024.0f);
    }
    __syncthreads();
    const float mu = bc;
    float q = 0.0f;
#pragma unroll
    for (int j = 0; j < 4; j++) { float d = v[j] - mu; q += d * d; }
    __syncthreads();
#pragma unroll
    for (int o = 16; o; o >>= 1) q += __shfl_xor_sync(0xffffffffu, q, o);
    if ((t & 31) == 0) red[t >> 5] = q;
    __syncthreads();
    if (t == 0) {
        float tt = 0;
#pragma unroll
        for (int i = 0; i < 8; i++) tt += red[i];
        bc2 = rsqrtf(tt * (1.0f / 1024.0f) + 1e-5f);
    }
    __syncthreads();
    const float rs = bc2;
#pragma unroll
    for (int j = 0; j < 4; j++) {
        int idx = t + j * 256;
        float o = (v[j] - mu) * rs * g[idx] + beta[idx];
        out[base + idx] = o;
        if (PL) {
            bf16 h, l; split2(o, h, l);
            oh[base + idx] = h; ol[base + idx] = l;
        }
    }
}

// ---------------------------------------------------------------------------
// Launch
// ---------------------------------------------------------------------------
extern "C" void kernel_launch(void* const* d_in, const int* in_sizes, int n_in,
                              void* d_out, int out_size) {
    const float* x     = (const float*)d_in[0];
    const void*  mask  = d_in[1];
    const float* wq    = (const float*)d_in[2];
    const float* wk    = (const float*)d_in[3];
    const float* wv    = (const float*)d_in[4];
    const float* fc_w  = (const float*)d_in[5];
    const float* fc_b  = (const float*)d_in[6];
    const float* w1    = (const float*)d_in[7];
    const float* b1    = (const float*)d_in[8];
    const float* w2    = (const float*)d_in[9];
    const float* b2    = (const float*)d_in[10];
    const float* ln1_g = (const float*)d_in[11];
    const float* ln1_b = (const float*)d_in[12];
    const float* ln2_g = (const float*)d_in[13];
    const float* ln2_b = (const float*)d_in[14];
    float* out = (float*)d_out;

    bf16 *Xh, *Xl, *Wqh, *Wql, *FCh, *FCl, *W1h, *W1l, *W2h, *W2l;
    bf16 *QKVh, *QKVl, *Vth, *Vtl, *Ph, *Pl, *Oh, *Ol, *X1h, *X1l, *H1h, *H1l;
    float *S, *ATT, *X1, *H2;
    cudaGetSymbolAddress((void**)&Xh, g_Xh);     cudaGetSymbolAddress((void**)&Xl, g_Xl);
    cudaGetSymbolAddress((void**)&Wqh, g_Wqkvh); cudaGetSymbolAddress((void**)&Wql, g_Wqkvl);
    cudaGetSymbolAddress((void**)&FCh, g_FCh);   cudaGetSymbolAddress((void**)&FCl, g_FCl);
    cudaGetSymbolAddress((void**)&W1h, g_W1h);   cudaGetSymbolAddress((void**)&W1l, g_W1l);
    cudaGetSymbolAddress((void**)&W2h, g_W2h);   cudaGetSymbolAddress((void**)&W2l, g_W2l);
    cudaGetSymbolAddress((void**)&QKVh, g_QKVh); cudaGetSymbolAddress((void**)&QKVl, g_QKVl);
    cudaGetSymbolAddress((void**)&Vth, g_Vth);   cudaGetSymbolAddress((void**)&Vtl, g_Vtl);
    cudaGetSymbolAddress((void**)&S, g_S);
    cudaGetSymbolAddress((void**)&Ph, g_Ph);     cudaGetSymbolAddress((void**)&Pl, g_Pl);
    cudaGetSymbolAddress((void**)&Oh, g_Oh);     cudaGetSymbolAddress((void**)&Ol, g_Ol);
    cudaGetSymbolAddress((void**)&ATT, g_ATT);
    cudaGetSymbolAddress((void**)&X1, g_X1);
    cudaGetSymbolAddress((void**)&X1h, g_X1h);   cudaGetSymbolAddress((void**)&X1l, g_X1l);
    cudaGetSymbolAddress((void**)&H1h, g_H1h);   cudaGetSymbolAddress((void**)&H1l, g_H1l);
    cudaGetSymbolAddress((void**)&H2, g_H2);

    constexpr int SM128 = 2 * 2 * (128 + 128) * 128;   // 131072
    constexpr int SM64  = 2 * 2 * (128 + 64) * 128;    //  98304
    cudaFuncSetAttribute(mma_gemm<128, 0>, cudaFuncAttributeMaxDynamicSharedMemorySize, SM128);
    cudaFuncSetAttribute(mma_gemm<128, 1>, cudaFuncAttributeMaxDynamicSharedMemorySize, SM128);
    cudaFuncSetAttribute(mma_gemm<128, 2>, cudaFuncAttributeMaxDynamicSharedMemorySize, SM128);
    cudaFuncSetAttribute(mma_gemm<128, 3>, cudaFuncAttributeMaxDynamicSharedMemorySize, SM128);
    cudaFuncSetAttribute(mma_gemm<64, 0>,  cudaFuncAttributeMaxDynamicSharedMemorySize, SM64);

    detect_mask_kernel<<<1, 256>>>((const unsigned int*)mask);

    // Input / weight splits
    split_kernel<<<(MR * Dsz / 4 + 255) / 256, 256>>>(x, Xh, Xl, (long long)MR * Dsz);
    pack_w_split<<<((long long)Dsz * NQ + 255) / 256, 256>>>(wq, wk, wv);
    split_kernel<<<((long long)Dsz * Dsz / 4 + 255) / 256, 256>>>(fc_w, FCh, FCl, (long long)Dsz * Dsz);
    split_kernel<<<((long long)FFsz * Dsz / 4 + 255) / 256, 256>>>(w1, W1h, W1l, (long long)FFsz * Dsz);
    split_kernel<<<((long long)Dsz * FFsz / 4 + 255) / 256, 256>>>(w2, W2h, W2l, (long long)Dsz * FFsz);

    // G1: QKV planes = X @ Wqkv^T
    mma_gemm<128, 0><<<dim3(NQ / 128, MR / 128, 1), 256, SM128>>>(
        Xh, Xl, Dsz, 0, 0, Wqh, Wql, Dsz, 0, 0,
        nullptr, QKVh, QKVl, NQ, 0, 0, Dsz, nullptr, nullptr);

    // V transpose into Vt planes
    vtrans_kernel<<<dim3(32, 2, 128), dim3(32, 8)>>>();

    // G2: S = Q @ K^T per (b,h), epilogue mask(-125) + *0.125 -> fp32
    mma_gemm<128, 1><<<dim3(Ssz / 128, Ssz / 128, Bsz * Hsz), 256, SM128>>>(
        QKVh, QKVl, NQ, (long long)Ssz * NQ, 64,
        QKVh + 1024, QKVl + 1024, NQ, (long long)Ssz * NQ, 64,
        S, nullptr, nullptr, Ssz, (long long)Hsz * Ssz * Ssz, (long long)Ssz * Ssz,
        DKsz, nullptr, mask);

    // Column softmax -> P planes
    col_softmax_kernel<<<dim3(Ssz / 64, Bsz * Hsz), 256>>>(S, Ph, Pl);

    // G3: O planes = P @ Vt^T per (b,h)
    mma_gemm<64, 0><<<dim3(1, Ssz / 128, Bsz * Hsz), 256, SM64>>>(
        Ph, Pl, Ssz, (long long)Hsz * Ssz * Ssz, (long long)Ssz * Ssz,
        Vth, Vtl, Ssz, (long long)Hsz * DKsz * Ssz, (long long)DKsz * Ssz,
        nullptr, Oh, Ol, Dsz, (long long)Ssz * Dsz, 64,
        Ssz, nullptr, nullptr);

    // G4: ATT = O @ fc_w^T + fc_b (fp32)
    mma_gemm<128, 2><<<dim3(Dsz / 128, MR / 128, 1), 256, SM128>>>(
        Oh, Ol, Dsz, 0, 0, FCh, FCl, Dsz, 0, 0,
        ATT, nullptr, nullptr, Dsz, 0, 0, Dsz, fc_b, nullptr);

    // LN1 -> X1 fp32 + planes
    ln_kernel<true><<<MR, 256>>>(ATT, x, ln1_g, ln1_b, X1, X1h, X1l);

    // G5: H1 planes = relu(X1 @ w1^T + b1)
    mma_gemm<128, 3><<<dim3(FFsz / 128, MR / 128, 1), 256, SM128>>>(
        X1h, X1l, Dsz, 0, 0, W1h, W1l, Dsz, 0, 0,
        nullptr, H1h, H1l, FFsz, 0, 0, Dsz, b1, nullptr);

    // G6: H2 = H1 @ w2^T + b2 (fp32)
    mma_gemm<128, 2><<<dim3(Dsz / 128, MR / 128, 1), 256, SM128>>>(
        H1h, H1l, FFsz, 0, 0, W2h, W2l, FFsz, 0, 0,
        H2, nullptr, nullptr, Dsz, 0, 0, FFsz, b2, nullptr);

    // LN2 -> out
    ln_kernel<false><<<MR, 256>>>(H2, X1, ln2_g, ln2_b, out, nullptr, nullptr);
}